// round 1
// baseline (speedup 1.0000x reference)
#include <cuda_runtime.h>
#include <math.h>

// Problem constants
#define BB   2
#define SS   2048
#define HH   8
#define HDIM 64
#define DD   512
#define WINW 64
#define SUBW 129
#define KSZ  2048
#define TT   (BB*SS)          // 4096 tokens
#define D3   (3*DD)           // 1536

// Scratch (device globals; allocation-free)
__device__ float g_kqv[TT * D3];     // 25 MB  (k | q | v per token row)
__device__ float g_ctx[TT * DD];     // 8.4 MB
__device__ float g_x1 [TT * KSZ];    // 33.5 MB

// ---------------------------------------------------------------------------
// Tiled SGEMM: C[M,N] = A[M,K] @ B[K,N] + bias  (+ epilogue)
// BM=BN=128, BK=8, 256 threads, 8x8 per-thread tile.
// EPI: 0 = bias, 1 = bias+relu, 2 = bias + residual
// ---------------------------------------------------------------------------
template <int EPI>
__global__ __launch_bounds__(256, 2)
void sgemm_k(const float* __restrict__ A, const float* __restrict__ Bm,
             const float* __restrict__ bias,
             const float* __restrict__ res, int resStride,
             float* __restrict__ C, int M, int N, int K)
{
    __shared__ float As[8][128];
    __shared__ float Bs[8][128];

    const int tid = threadIdx.x;
    const int bx  = blockIdx.x;   // N tile
    const int by  = blockIdx.y;   // M tile

    // load indices (float4)
    const int aRow = tid >> 1;          // 0..127
    const int aCol = (tid & 1) << 2;    // 0 or 4
    const int bRow = tid >> 5;          // 0..7
    const int bCol = (tid & 31) << 2;   // 0..124

    // compute indices
    const int tr = tid >> 4;            // 0..15
    const int tc = tid & 15;            // 0..15

    float acc[8][8];
    #pragma unroll
    for (int i = 0; i < 8; i++)
        #pragma unroll
        for (int j = 0; j < 8; j++) acc[i][j] = 0.f;

    const float* Aptr = A + (size_t)(by * 128 + aRow) * K + aCol;
    const float* Bptr = Bm + (size_t)bRow * N + bx * 128 + bCol;

    for (int k0 = 0; k0 < K; k0 += 8) {
        float4 a4 = *reinterpret_cast<const float4*>(Aptr + k0);
        As[aCol + 0][aRow] = a4.x;
        As[aCol + 1][aRow] = a4.y;
        As[aCol + 2][aRow] = a4.z;
        As[aCol + 3][aRow] = a4.w;
        float4 b4 = *reinterpret_cast<const float4*>(Bptr + (size_t)k0 * N);
        *reinterpret_cast<float4*>(&Bs[bRow][bCol]) = b4;
        __syncthreads();

        #pragma unroll
        for (int kk = 0; kk < 8; kk++) {
            float ra[8], rb[8];
            float4 ra0 = *reinterpret_cast<const float4*>(&As[kk][tr * 8]);
            float4 ra1 = *reinterpret_cast<const float4*>(&As[kk][tr * 8 + 4]);
            ra[0]=ra0.x; ra[1]=ra0.y; ra[2]=ra0.z; ra[3]=ra0.w;
            ra[4]=ra1.x; ra[5]=ra1.y; ra[6]=ra1.z; ra[7]=ra1.w;
            float4 rb0 = *reinterpret_cast<const float4*>(&Bs[kk][tc * 8]);
            float4 rb1 = *reinterpret_cast<const float4*>(&Bs[kk][tc * 8 + 4]);
            rb[0]=rb0.x; rb[1]=rb0.y; rb[2]=rb0.z; rb[3]=rb0.w;
            rb[4]=rb1.x; rb[5]=rb1.y; rb[6]=rb1.z; rb[7]=rb1.w;
            #pragma unroll
            for (int i = 0; i < 8; i++)
                #pragma unroll
                for (int j = 0; j < 8; j++)
                    acc[i][j] = fmaf(ra[i], rb[j], acc[i][j]);
        }
        __syncthreads();
    }

    const int row0 = by * 128 + tr * 8;
    const int col0 = bx * 128 + tc * 8;
    #pragma unroll
    for (int i = 0; i < 8; i++) {
        const int row = row0 + i;
        #pragma unroll
        for (int j4 = 0; j4 < 8; j4 += 4) {
            float4 o;
            o.x = acc[i][j4 + 0] + bias[col0 + j4 + 0];
            o.y = acc[i][j4 + 1] + bias[col0 + j4 + 1];
            o.z = acc[i][j4 + 2] + bias[col0 + j4 + 2];
            o.w = acc[i][j4 + 3] + bias[col0 + j4 + 3];
            if (EPI == 1) {
                o.x = fmaxf(o.x, 0.f); o.y = fmaxf(o.y, 0.f);
                o.z = fmaxf(o.z, 0.f); o.w = fmaxf(o.w, 0.f);
            }
            if (EPI == 2) {
                const float* rp = res + (size_t)row * resStride + col0 + j4;
                o.x += rp[0]; o.y += rp[1]; o.z += rp[2]; o.w += rp[3];
            }
            *reinterpret_cast<float4*>(&C[(size_t)row * N + col0 + j4]) = o;
        }
    }
}

// ---------------------------------------------------------------------------
// LayerNorm in place on k (cols 0..511) and q (cols 512..1023) of g_kqv.
// grid (TT, 2), 128 threads, 4 elems/thread.
// ---------------------------------------------------------------------------
__global__ void ln_kernel(float* __restrict__ kqv,
                          const float* __restrict__ gamma,
                          const float* __restrict__ beta)
{
    const int t   = blockIdx.x;
    const int sel = blockIdx.y;          // 0=k, 1=q
    float* row = kqv + (size_t)t * D3 + sel * DD;
    const int tid = threadIdx.x;

    float4 v = reinterpret_cast<float4*>(row)[tid];
    float s  = v.x + v.y + v.z + v.w;
    float sq = v.x*v.x + v.y*v.y + v.z*v.z + v.w*v.w;

    #pragma unroll
    for (int o = 16; o; o >>= 1) {
        s  += __shfl_xor_sync(0xffffffffu, s,  o);
        sq += __shfl_xor_sync(0xffffffffu, sq, o);
    }
    __shared__ float rs[4], rq[4];
    if ((tid & 31) == 0) { rs[tid >> 5] = s; rq[tid >> 5] = sq; }
    __syncthreads();
    s  = rs[0] + rs[1] + rs[2] + rs[3];
    sq = rq[0] + rq[1] + rq[2] + rq[3];

    const float mean = s * (1.0f / DD);
    const float var  = sq * (1.0f / DD) - mean * mean;
    const float inv  = rsqrtf(var + 1e-3f);

    const int e = tid * 4;
    float4 g = reinterpret_cast<const float4*>(gamma)[tid];
    float4 b = reinterpret_cast<const float4*>(beta)[tid];
    (void)e;
    v.x = (v.x - mean) * inv * g.x + b.x;
    v.y = (v.y - mean) * inv * g.y + b.y;
    v.z = (v.z - mean) * inv * g.z + b.z;
    v.w = (v.w - mean) * inv * g.w + b.w;
    reinterpret_cast<float4*>(row)[tid] = v;
}

// ---------------------------------------------------------------------------
// Sliding-window attention. grid (TT, H), 128 threads.
// q from kqv cols [512,1024), k cols [0,512), v cols [1024,1536).
// ---------------------------------------------------------------------------
__global__ void attn_kernel(const float* __restrict__ kqv,
                            float* __restrict__ ctx)
{
    const int t = blockIdx.x;            // global token 0..4095
    const int h = blockIdx.y;
    const int b = t >> 11;               // /2048
    const int s = t & 2047;
    int start = s - WINW;
    if (start < 0) start = 0;
    if (start > SS - SUBW) start = SS - SUBW;
    const int base = b << 11;            // b*S

    __shared__ float qs[HDIM];
    __shared__ float sc[SUBW];
    __shared__ float red[4];

    const int tid = threadIdx.x;
    if (tid < HDIM)
        qs[tid] = kqv[(size_t)t * D3 + DD + h * HDIM + tid];
    __syncthreads();

    // scores
    float lmax = -1e30f;
    for (int j = tid; j < SUBW; j += 128) {
        const float* kp = kqv + (size_t)(base + start + j) * D3 + h * HDIM;
        float acc = 0.f;
        #pragma unroll
        for (int i = 0; i < HDIM; i++) acc = fmaf(qs[i], kp[i], acc);
        acc *= 0.125f;                    // 1/sqrt(64)
        sc[j] = acc;
        lmax = fmaxf(lmax, acc);
    }
    // block max
    #pragma unroll
    for (int o = 16; o; o >>= 1) lmax = fmaxf(lmax, __shfl_xor_sync(0xffffffffu, lmax, o));
    if ((tid & 31) == 0) red[tid >> 5] = lmax;
    __syncthreads();
    lmax = fmaxf(fmaxf(red[0], red[1]), fmaxf(red[2], red[3]));
    __syncthreads();

    float lsum = 0.f;
    for (int j = tid; j < SUBW; j += 128) {
        float e = expf(sc[j] - lmax);
        sc[j] = e;
        lsum += e;
    }
    #pragma unroll
    for (int o = 16; o; o >>= 1) lsum += __shfl_xor_sync(0xffffffffu, lsum, o);
    if ((tid & 31) == 0) red[tid >> 5] = lsum;
    __syncthreads();
    lsum = red[0] + red[1] + red[2] + red[3];
    const float inv = 1.0f / lsum;
    __syncthreads();
    for (int j = tid; j < SUBW; j += 128) sc[j] *= inv;
    __syncthreads();

    // ctx: coalesced over head dim
    if (tid < HDIM) {
        float acc = 0.f;
        const float* vp = kqv + (size_t)(base + start) * D3 + 2 * DD + h * HDIM + tid;
        #pragma unroll 4
        for (int j = 0; j < SUBW; j++)
            acc = fmaf(sc[j], vp[(size_t)j * D3], acc);
        ctx[(size_t)t * DD + h * HDIM + tid] = acc;
    }
}

// ---------------------------------------------------------------------------
extern "C" void kernel_launch(void* const* d_in, const int* in_sizes, int n_in,
                              void* d_out, int out_size)
{
    const float* values   = (const float*)d_in[0];
    const float* W_kqv    = (const float*)d_in[1];
    const float* b_kqv    = (const float*)d_in[2];
    const float* ln_gamma = (const float*)d_in[3];
    const float* ln_beta  = (const float*)d_in[4];
    const float* W_kernel = (const float*)d_in[5];
    const float* b_kernel = (const float*)d_in[6];
    const float* W_proj   = (const float*)d_in[7];
    const float* b_proj   = (const float*)d_in[8];
    float* out = (float*)d_out;

    float *kqv, *ctx, *x1;
    cudaGetSymbolAddress((void**)&kqv, g_kqv);
    cudaGetSymbolAddress((void**)&ctx, g_ctx);
    cudaGetSymbolAddress((void**)&x1,  g_x1);

    // 1) kqv = values @ W_kqv + b_kqv
    sgemm_k<0><<<dim3(D3 / 128, TT / 128), 256>>>(
        values, W_kqv, b_kqv, nullptr, 0, kqv, TT, D3, DD);

    // 2) LayerNorm q and k in place
    ln_kernel<<<dim3(TT, 2), 128>>>(kqv, ln_gamma, ln_beta);

    // 3) sliding-window attention -> ctx
    attn_kernel<<<dim3(TT, HH), 128>>>(kqv, ctx);

    // 4) x1 = relu(ctx @ W_kernel + b_kernel)
    sgemm_k<1><<<dim3(KSZ / 128, TT / 128), 256>>>(
        ctx, W_kernel, b_kernel, nullptr, 0, x1, TT, KSZ, DD);

    // 5) out = x1 @ W_proj + b_proj + v   (v = kqv cols [1024,1536))
    sgemm_k<2><<<dim3(DD / 128, TT / 128), 256>>>(
        x1, W_proj, b_proj, kqv + 2 * DD, D3, out, TT, DD, KSZ);
}

// round 2
// speedup vs baseline: 2.1867x; 2.1867x over previous
#include <cuda_runtime.h>
#include <math.h>

// Problem constants
#define BB   2
#define SS   2048
#define HH   8
#define HDIM 64
#define DD   512
#define WINW 64
#define SUBW 129
#define KSZ  2048
#define TT   (BB*SS)          // 4096 tokens
#define D3   (3*DD)           // 1536

// Attention tile constants
#define QT   32               // queries per block
#define KW   160              // key window span per tile (129 + 31)
#define KSTR 68               // padded float stride for K/V/Q rows
#define PSTR 168              // padded float stride for P rows

// Scratch (device globals; allocation-free)
__device__ float g_kqv[TT * D3];     // 25 MB  (k | q | v per token row)
__device__ float g_ctx[TT * DD];     // 8.4 MB
__device__ float g_x1 [TT * KSZ];    // 33.5 MB

// ---------------------------------------------------------------------------
// Tiled SGEMM: C[M,N] = A[M,K] @ B[K,N] + bias  (+ epilogue)
// BM=BN=128, BK=8, 256 threads, 8x8 per-thread tile.
// EPI: 0 = bias, 1 = bias+relu, 2 = bias + residual
// ---------------------------------------------------------------------------
template <int EPI>
__global__ __launch_bounds__(256, 2)
void sgemm_k(const float* __restrict__ A, const float* __restrict__ Bm,
             const float* __restrict__ bias,
             const float* __restrict__ res, int resStride,
             float* __restrict__ C, int M, int N, int K)
{
    __shared__ float As[8][128];
    __shared__ float Bs[8][128];

    const int tid = threadIdx.x;
    const int bx  = blockIdx.x;   // N tile
    const int by  = blockIdx.y;   // M tile

    const int aRow = tid >> 1;          // 0..127
    const int aCol = (tid & 1) << 2;    // 0 or 4
    const int bRow = tid >> 5;          // 0..7
    const int bCol = (tid & 31) << 2;   // 0..124

    const int tr = tid >> 4;            // 0..15
    const int tc = tid & 15;            // 0..15

    float acc[8][8];
    #pragma unroll
    for (int i = 0; i < 8; i++)
        #pragma unroll
        for (int j = 0; j < 8; j++) acc[i][j] = 0.f;

    const float* Aptr = A + (size_t)(by * 128 + aRow) * K + aCol;
    const float* Bptr = Bm + (size_t)bRow * N + bx * 128 + bCol;

    for (int k0 = 0; k0 < K; k0 += 8) {
        float4 a4 = *reinterpret_cast<const float4*>(Aptr + k0);
        As[aCol + 0][aRow] = a4.x;
        As[aCol + 1][aRow] = a4.y;
        As[aCol + 2][aRow] = a4.z;
        As[aCol + 3][aRow] = a4.w;
        float4 b4 = *reinterpret_cast<const float4*>(Bptr + (size_t)k0 * N);
        *reinterpret_cast<float4*>(&Bs[bRow][bCol]) = b4;
        __syncthreads();

        #pragma unroll
        for (int kk = 0; kk < 8; kk++) {
            float ra[8], rb[8];
            float4 ra0 = *reinterpret_cast<const float4*>(&As[kk][tr * 8]);
            float4 ra1 = *reinterpret_cast<const float4*>(&As[kk][tr * 8 + 4]);
            ra[0]=ra0.x; ra[1]=ra0.y; ra[2]=ra0.z; ra[3]=ra0.w;
            ra[4]=ra1.x; ra[5]=ra1.y; ra[6]=ra1.z; ra[7]=ra1.w;
            float4 rb0 = *reinterpret_cast<const float4*>(&Bs[kk][tc * 8]);
            float4 rb1 = *reinterpret_cast<const float4*>(&Bs[kk][tc * 8 + 4]);
            rb[0]=rb0.x; rb[1]=rb0.y; rb[2]=rb0.z; rb[3]=rb0.w;
            rb[4]=rb1.x; rb[5]=rb1.y; rb[6]=rb1.z; rb[7]=rb1.w;
            #pragma unroll
            for (int i = 0; i < 8; i++)
                #pragma unroll
                for (int j = 0; j < 8; j++)
                    acc[i][j] = fmaf(ra[i], rb[j], acc[i][j]);
        }
        __syncthreads();
    }

    const int row0 = by * 128 + tr * 8;
    const int col0 = bx * 128 + tc * 8;
    #pragma unroll
    for (int i = 0; i < 8; i++) {
        const int row = row0 + i;
        #pragma unroll
        for (int j4 = 0; j4 < 8; j4 += 4) {
            float4 o;
            o.x = acc[i][j4 + 0] + bias[col0 + j4 + 0];
            o.y = acc[i][j4 + 1] + bias[col0 + j4 + 1];
            o.z = acc[i][j4 + 2] + bias[col0 + j4 + 2];
            o.w = acc[i][j4 + 3] + bias[col0 + j4 + 3];
            if (EPI == 1) {
                o.x = fmaxf(o.x, 0.f); o.y = fmaxf(o.y, 0.f);
                o.z = fmaxf(o.z, 0.f); o.w = fmaxf(o.w, 0.f);
            }
            if (EPI == 2) {
                const float* rp = res + (size_t)row * resStride + col0 + j4;
                o.x += rp[0]; o.y += rp[1]; o.z += rp[2]; o.w += rp[3];
            }
            *reinterpret_cast<float4*>(&C[(size_t)row * N + col0 + j4]) = o;
        }
    }
}

// ---------------------------------------------------------------------------
// LayerNorm in place on k (cols 0..511) and q (cols 512..1023) of g_kqv.
// ---------------------------------------------------------------------------
__global__ void ln_kernel(float* __restrict__ kqv,
                          const float* __restrict__ gamma,
                          const float* __restrict__ beta)
{
    const int t   = blockIdx.x;
    const int sel = blockIdx.y;          // 0=k, 1=q
    float* row = kqv + (size_t)t * D3 + sel * DD;
    const int tid = threadIdx.x;

    float4 v = reinterpret_cast<float4*>(row)[tid];
    float s  = v.x + v.y + v.z + v.w;
    float sq = v.x*v.x + v.y*v.y + v.z*v.z + v.w*v.w;

    #pragma unroll
    for (int o = 16; o; o >>= 1) {
        s  += __shfl_xor_sync(0xffffffffu, s,  o);
        sq += __shfl_xor_sync(0xffffffffu, sq, o);
    }
    __shared__ float rs[4], rq[4];
    if ((tid & 31) == 0) { rs[tid >> 5] = s; rq[tid >> 5] = sq; }
    __syncthreads();
    s  = rs[0] + rs[1] + rs[2] + rs[3];
    sq = rq[0] + rq[1] + rq[2] + rq[3];

    const float mean = s * (1.0f / DD);
    const float var  = sq * (1.0f / DD) - mean * mean;
    const float inv  = rsqrtf(var + 1e-3f);

    float4 g = reinterpret_cast<const float4*>(gamma)[tid];
    float4 b = reinterpret_cast<const float4*>(beta)[tid];
    v.x = (v.x - mean) * inv * g.x + b.x;
    v.y = (v.y - mean) * inv * g.y + b.y;
    v.z = (v.z - mean) * inv * g.z + b.z;
    v.w = (v.w - mean) * inv * g.w + b.w;
    reinterpret_cast<float4*>(row)[tid] = v;
}

// ---------------------------------------------------------------------------
// Tiled sliding-window attention.
// Block = (q-tile of 32, head, batch), 256 threads.
// Stages Q(32x64), K(160x64), V(160x64) in smem; scores in registers
// (2 rows x 10 cols per thread); softmax via 16-lane shuffles; P staged
// in smem (reusing K region); ctx = P @ V with 2x4 register tiles.
// ---------------------------------------------------------------------------
__global__ __launch_bounds__(256, 2)
void attn_tile_kernel(const float* __restrict__ kqv, float* __restrict__ ctx)
{
    extern __shared__ float sm[];
    float* Ksm = sm;                         // [KW][KSTR]
    float* Vsm = sm + KW * KSTR;             // [KW][KSTR]
    float* Qsm = sm + 2 * KW * KSTR;         // [QT][KSTR]
    float* Psm = sm;                         // [QT][PSTR] (overlaps Ksm)

    const int tid  = threadIdx.x;
    const int tile = blockIdx.x;             // 0..S/QT-1
    const int h    = blockIdx.y;
    const int b    = blockIdx.z;

    const int t0 = tile * QT;
    int kbase = t0 - WINW;
    if (kbase < 0) kbase = 0;
    if (kbase > SS - KW) kbase = SS - KW;
    const size_t rowBase = (size_t)(b * SS) * D3 + h * HDIM;

    // ---- stage K, V, Q (coalesced float4) ----
    {
        const int r0 = tid >> 4;             // 16 rows per pass
        const int c4 = (tid & 15) << 2;      // float4 col in [0,64)
        #pragma unroll
        for (int r = r0; r < KW; r += 16) {
            const float* src = kqv + rowBase + (size_t)(kbase + r) * D3;
            *reinterpret_cast<float4*>(Ksm + r * KSTR + c4) =
                *reinterpret_cast<const float4*>(src + c4);
            *reinterpret_cast<float4*>(Vsm + r * KSTR + c4) =
                *reinterpret_cast<const float4*>(src + 2 * DD + c4);
        }
        #pragma unroll
        for (int r = r0; r < QT; r += 16) {
            const float* src = kqv + rowBase + (size_t)(t0 + r) * D3 + DD;
            *reinterpret_cast<float4*>(Qsm + r * KSTR + c4) =
                *reinterpret_cast<const float4*>(src + c4);
        }
    }
    __syncthreads();

    // ---- scores: thread (tr, tc): rows {2tr, 2tr+1}, cols {10tc..10tc+9} ----
    const int tr = tid >> 4;                 // 0..15
    const int tc = tid & 15;                 // 0..15

    float acc[2][10];
    #pragma unroll
    for (int i = 0; i < 2; i++)
        #pragma unroll
        for (int j = 0; j < 10; j++) acc[i][j] = 0.f;

    #pragma unroll
    for (int k4 = 0; k4 < HDIM; k4 += 4) {
        float4 qa0 = *reinterpret_cast<const float4*>(Qsm + (tr * 2 + 0) * KSTR + k4);
        float4 qa1 = *reinterpret_cast<const float4*>(Qsm + (tr * 2 + 1) * KSTR + k4);
        #pragma unroll
        for (int j = 0; j < 10; j++) {
            float4 kb = *reinterpret_cast<const float4*>(Ksm + (tc * 10 + j) * KSTR + k4);
            acc[0][j] = fmaf(qa0.x, kb.x, acc[0][j]);
            acc[0][j] = fmaf(qa0.y, kb.y, acc[0][j]);
            acc[0][j] = fmaf(qa0.z, kb.z, acc[0][j]);
            acc[0][j] = fmaf(qa0.w, kb.w, acc[0][j]);
            acc[1][j] = fmaf(qa1.x, kb.x, acc[1][j]);
            acc[1][j] = fmaf(qa1.y, kb.y, acc[1][j]);
            acc[1][j] = fmaf(qa1.z, kb.z, acc[1][j]);
            acc[1][j] = fmaf(qa1.w, kb.w, acc[1][j]);
        }
    }

    // ---- mask + softmax (per row; 16 lanes share a row) ----
    float inv[2];
    #pragma unroll
    for (int i = 0; i < 2; i++) {
        const int s = t0 + tr * 2 + i;
        int start = s - WINW;
        if (start < 0) start = 0;
        if (start > SS - SUBW) start = SS - SUBW;
        const int off = start - kbase;       // valid cols: [off, off+SUBW)

        float mx = -1e30f;
        #pragma unroll
        for (int j = 0; j < 10; j++) {
            const int c = tc * 10 + j;
            float scv = acc[i][j] * 0.125f;   // 1/sqrt(64)
            if (c < off || c >= off + SUBW) scv = -1e30f;
            acc[i][j] = scv;
            mx = fmaxf(mx, scv);
        }
        #pragma unroll
        for (int o = 1; o < 16; o <<= 1)
            mx = fmaxf(mx, __shfl_xor_sync(0xffffffffu, mx, o));

        float sum = 0.f;
        #pragma unroll
        for (int j = 0; j < 10; j++) {
            float e = __expf(acc[i][j] - mx);
            acc[i][j] = e;
            sum += e;
        }
        #pragma unroll
        for (int o = 1; o < 16; o <<= 1)
            sum += __shfl_xor_sync(0xffffffffu, sum, o);
        inv[i] = 1.0f / sum;
    }

    __syncthreads();   // everyone done reading Ksm before P overwrites it

    #pragma unroll
    for (int i = 0; i < 2; i++) {
        float* prow = Psm + (tr * 2 + i) * PSTR + tc * 10;
        #pragma unroll
        for (int j = 0; j < 10; j++) prow[j] = acc[i][j] * inv[i];
    }
    __syncthreads();

    // ---- ctx = P(32x160) @ V(160x64): thread = 2 rows x 4 cols ----
    const int orr = tid >> 4;                // rows {2orr, 2orr+1}
    const int oc4 = (tid & 15) << 2;         // col group

    float oacc[2][4];
    #pragma unroll
    for (int i = 0; i < 2; i++)
        #pragma unroll
        for (int j = 0; j < 4; j++) oacc[i][j] = 0.f;

    #pragma unroll 4
    for (int k4 = 0; k4 < KW; k4 += 4) {
        float4 pa0 = *reinterpret_cast<const float4*>(Psm + (orr * 2 + 0) * PSTR + k4);
        float4 pa1 = *reinterpret_cast<const float4*>(Psm + (orr * 2 + 1) * PSTR + k4);
        float4 vb0 = *reinterpret_cast<const float4*>(Vsm + (k4 + 0) * KSTR + oc4);
        float4 vb1 = *reinterpret_cast<const float4*>(Vsm + (k4 + 1) * KSTR + oc4);
        float4 vb2 = *reinterpret_cast<const float4*>(Vsm + (k4 + 2) * KSTR + oc4);
        float4 vb3 = *reinterpret_cast<const float4*>(Vsm + (k4 + 3) * KSTR + oc4);

        oacc[0][0] = fmaf(pa0.x, vb0.x, oacc[0][0]);
        oacc[0][1] = fmaf(pa0.x, vb0.y, oacc[0][1]);
        oacc[0][2] = fmaf(pa0.x, vb0.z, oacc[0][2]);
        oacc[0][3] = fmaf(pa0.x, vb0.w, oacc[0][3]);
        oacc[0][0] = fmaf(pa0.y, vb1.x, oacc[0][0]);
        oacc[0][1] = fmaf(pa0.y, vb1.y, oacc[0][1]);
        oacc[0][2] = fmaf(pa0.y, vb1.z, oacc[0][2]);
        oacc[0][3] = fmaf(pa0.y, vb1.w, oacc[0][3]);
        oacc[0][0] = fmaf(pa0.z, vb2.x, oacc[0][0]);
        oacc[0][1] = fmaf(pa0.z, vb2.y, oacc[0][1]);
        oacc[0][2] = fmaf(pa0.z, vb2.z, oacc[0][2]);
        oacc[0][3] = fmaf(pa0.z, vb2.w, oacc[0][3]);
        oacc[0][0] = fmaf(pa0.w, vb3.x, oacc[0][0]);
        oacc[0][1] = fmaf(pa0.w, vb3.y, oacc[0][1]);
        oacc[0][2] = fmaf(pa0.w, vb3.z, oacc[0][2]);
        oacc[0][3] = fmaf(pa0.w, vb3.w, oacc[0][3]);

        oacc[1][0] = fmaf(pa1.x, vb0.x, oacc[1][0]);
        oacc[1][1] = fmaf(pa1.x, vb0.y, oacc[1][1]);
        oacc[1][2] = fmaf(pa1.x, vb0.z, oacc[1][2]);
        oacc[1][3] = fmaf(pa1.x, vb0.w, oacc[1][3]);
        oacc[1][0] = fmaf(pa1.y, vb1.x, oacc[1][0]);
        oacc[1][1] = fmaf(pa1.y, vb1.y, oacc[1][1]);
        oacc[1][2] = fmaf(pa1.y, vb1.z, oacc[1][2]);
        oacc[1][3] = fmaf(pa1.y, vb1.w, oacc[1][3]);
        oacc[1][0] = fmaf(pa1.z, vb2.x, oacc[1][0]);
        oacc[1][1] = fmaf(pa1.z, vb2.y, oacc[1][1]);
        oacc[1][2] = fmaf(pa1.z, vb2.z, oacc[1][2]);
        oacc[1][3] = fmaf(pa1.z, vb2.w, oacc[1][3]);
        oacc[1][0] = fmaf(pa1.w, vb3.x, oacc[1][0]);
        oacc[1][1] = fmaf(pa1.w, vb3.y, oacc[1][1]);
        oacc[1][2] = fmaf(pa1.w, vb3.z, oacc[1][2]);
        oacc[1][3] = fmaf(pa1.w, vb3.w, oacc[1][3]);
    }

    #pragma unroll
    for (int i = 0; i < 2; i++) {
        float* dst = ctx + (size_t)(b * SS + t0 + orr * 2 + i) * DD + h * HDIM + oc4;
        float4 o;
        o.x = oacc[i][0]; o.y = oacc[i][1]; o.z = oacc[i][2]; o.w = oacc[i][3];
        *reinterpret_cast<float4*>(dst) = o;
    }
}

// ---------------------------------------------------------------------------
extern "C" void kernel_launch(void* const* d_in, const int* in_sizes, int n_in,
                              void* d_out, int out_size)
{
    const float* values   = (const float*)d_in[0];
    const float* W_kqv    = (const float*)d_in[1];
    const float* b_kqv    = (const float*)d_in[2];
    const float* ln_gamma = (const float*)d_in[3];
    const float* ln_beta  = (const float*)d_in[4];
    const float* W_kernel = (const float*)d_in[5];
    const float* b_kernel = (const float*)d_in[6];
    const float* W_proj   = (const float*)d_in[7];
    const float* b_proj   = (const float*)d_in[8];
    float* out = (float*)d_out;

    float *kqv, *ctx, *x1;
    cudaGetSymbolAddress((void**)&kqv, g_kqv);
    cudaGetSymbolAddress((void**)&ctx, g_ctx);
    cudaGetSymbolAddress((void**)&x1,  g_x1);

    const int attnSmem = (2 * KW * KSTR + QT * KSTR) * sizeof(float);  // ~93.5 KB
    static bool attrSet = false;
    if (!attrSet) {
        cudaFuncSetAttribute(attn_tile_kernel,
                             cudaFuncAttributeMaxDynamicSharedMemorySize, attnSmem);
        attrSet = true;
    }

    // 1) kqv = values @ W_kqv + b_kqv
    sgemm_k<0><<<dim3(D3 / 128, TT / 128), 256>>>(
        values, W_kqv, b_kqv, nullptr, 0, kqv, TT, D3, DD);

    // 2) LayerNorm q and k in place
    ln_kernel<<<dim3(TT, 2), 128>>>(kqv, ln_gamma, ln_beta);

    // 3) tiled sliding-window attention -> ctx
    attn_tile_kernel<<<dim3(SS / QT, HH, BB), 256, attnSmem>>>(kqv, ctx);

    // 4) x1 = relu(ctx @ W_kernel + b_kernel)
    sgemm_k<1><<<dim3(KSZ / 128, TT / 128), 256>>>(
        ctx, W_kernel, b_kernel, nullptr, 0, x1, TT, KSZ, DD);

    // 5) out = x1 @ W_proj + b_proj + v   (v = kqv cols [1024,1536))
    sgemm_k<2><<<dim3(DD / 128, TT / 128), 256>>>(
        x1, W_proj, b_proj, kqv + 2 * DD, D3, out, TT, DD, KSZ);
}

// round 3
// speedup vs baseline: 3.3083x; 1.5129x over previous
#include <cuda_runtime.h>
#include <mma.h>
#include <math.h>

using namespace nvcuda;

// Problem constants
#define BB   2
#define SS   2048
#define HH   8
#define HDIM 64
#define DD   512
#define WINW 64
#define SUBW 129
#define KSZ  2048
#define TT   (BB*SS)          // 4096 tokens
#define D3   (3*DD)           // 1536

// Attention tile constants
#define QT   32
#define KW   160
#define KSTR 68
#define PSTR 168

// wmma GEMM tile constants
#define BKG  16               // k tile
#define ASTR 20               // A smem stride (128 rows x BKG cols)
#define BSTR 132              // B smem stride (BKG rows x 128 cols)
#define CSTR 132              // C smem stride

// Scratch (device globals; allocation-free)
__device__ float g_kqv[TT * D3];
__device__ float g_ctx[TT * DD];
__device__ float g_x1 [TT * KSZ];

// ---------------------------------------------------------------------------
// tf32 tensor-core GEMM: C[M,N] = A[M,K] @ B[K,N] + bias (+ epilogue)
// BM=BN=128, BK=16, 256 threads (8 warps), warp tile 64x32 (4x2 wmma frags).
// Double-buffered smem; epilogue staged through smem C tile.
// EPI: 0 = bias, 1 = bias+relu, 2 = bias + residual
// ---------------------------------------------------------------------------
template <int EPI>
__global__ __launch_bounds__(256)
void tgemm_k(const float* __restrict__ A, const float* __restrict__ Bm,
             const float* __restrict__ bias,
             const float* __restrict__ res, int resStride,
             float* __restrict__ C, int M, int N, int K)
{
    extern __shared__ float sm[];
    float* As[2] = { sm,                sm + 128 * ASTR };
    float* Bs[2] = { sm + 2*128*ASTR,   sm + 2*128*ASTR + BKG * BSTR };
    float* Cs    = sm;    // aliases load buffers; used only after final sync

    const int tid    = threadIdx.x;
    const int warpId = tid >> 5;
    const int warpM  = warpId & 1;      // 0..1 : 64-row block
    const int warpN  = warpId >> 1;     // 0..3 : 32-col block

    const int blockN = blockIdx.x * 128;
    const int blockM = blockIdx.y * 128;

    // global load mapping
    const int aRow = tid >> 2;               // 0..63 (two passes: +64)
    const int aCol = (tid & 3) << 2;         // 0,4,8,12
    const int bRow = tid >> 5;               // 0..7  (two passes: +8)
    const int bCol = (tid & 31) << 2;        // 0..124

    const float* Ap = A + (size_t)(blockM + aRow) * K + aCol;
    const float* Bp = Bm + (size_t)bRow * N + blockN + bCol;

    wmma::fragment<wmma::accumulator, 16, 16, 8, float> acc[4][2];
    #pragma unroll
    for (int i = 0; i < 4; i++)
        #pragma unroll
        for (int j = 0; j < 2; j++) wmma::fill_fragment(acc[i][j], 0.f);

    float4 pa0, pa1, pb0, pb1;

    // prologue: load tile k0=0
    pa0 = *reinterpret_cast<const float4*>(Ap);
    pa1 = *reinterpret_cast<const float4*>(Ap + (size_t)64 * K);
    pb0 = *reinterpret_cast<const float4*>(Bp);
    pb1 = *reinterpret_cast<const float4*>(Bp + (size_t)8 * N);
    {
        float* dstA0 = As[0] + aRow * ASTR + aCol;
        float* dstA1 = As[0] + (aRow + 64) * ASTR + aCol;
        dstA0[0]=wmma::__float_to_tf32(pa0.x); dstA0[1]=wmma::__float_to_tf32(pa0.y);
        dstA0[2]=wmma::__float_to_tf32(pa0.z); dstA0[3]=wmma::__float_to_tf32(pa0.w);
        dstA1[0]=wmma::__float_to_tf32(pa1.x); dstA1[1]=wmma::__float_to_tf32(pa1.y);
        dstA1[2]=wmma::__float_to_tf32(pa1.z); dstA1[3]=wmma::__float_to_tf32(pa1.w);
        float* dstB0 = Bs[0] + bRow * BSTR + bCol;
        float* dstB1 = Bs[0] + (bRow + 8) * BSTR + bCol;
        dstB0[0]=wmma::__float_to_tf32(pb0.x); dstB0[1]=wmma::__float_to_tf32(pb0.y);
        dstB0[2]=wmma::__float_to_tf32(pb0.z); dstB0[3]=wmma::__float_to_tf32(pb0.w);
        dstB1[0]=wmma::__float_to_tf32(pb1.x); dstB1[1]=wmma::__float_to_tf32(pb1.y);
        dstB1[2]=wmma::__float_to_tf32(pb1.z); dstB1[3]=wmma::__float_to_tf32(pb1.w);
    }
    __syncthreads();

    int cur = 0;
    for (int k0 = 0; k0 < K; k0 += BKG) {
        const bool more = (k0 + BKG) < K;
        if (more) {
            const float* Ap2 = Ap + k0 + BKG;
            const float* Bp2 = Bp + (size_t)(k0 + BKG) * N;
            pa0 = *reinterpret_cast<const float4*>(Ap2);
            pa1 = *reinterpret_cast<const float4*>(Ap2 + (size_t)64 * K);
            pb0 = *reinterpret_cast<const float4*>(Bp2);
            pb1 = *reinterpret_cast<const float4*>(Bp2 + (size_t)8 * N);
        }

        // compute on buffer `cur`
        #pragma unroll
        for (int kk = 0; kk < BKG; kk += 8) {
            wmma::fragment<wmma::matrix_a, 16, 16, 8, wmma::precision::tf32, wmma::row_major> af[4];
            wmma::fragment<wmma::matrix_b, 16, 16, 8, wmma::precision::tf32, wmma::row_major> bf[2];
            #pragma unroll
            for (int i = 0; i < 4; i++)
                wmma::load_matrix_sync(af[i],
                    As[cur] + (warpM * 64 + i * 16) * ASTR + kk, ASTR);
            #pragma unroll
            for (int j = 0; j < 2; j++)
                wmma::load_matrix_sync(bf[j],
                    Bs[cur] + kk * BSTR + warpN * 32 + j * 16, BSTR);
            #pragma unroll
            for (int i = 0; i < 4; i++)
                #pragma unroll
                for (int j = 0; j < 2; j++)
                    wmma::mma_sync(acc[i][j], af[i], bf[j], acc[i][j]);
        }

        if (more) {
            const int nxt = cur ^ 1;
            float* dstA0 = As[nxt] + aRow * ASTR + aCol;
            float* dstA1 = As[nxt] + (aRow + 64) * ASTR + aCol;
            dstA0[0]=wmma::__float_to_tf32(pa0.x); dstA0[1]=wmma::__float_to_tf32(pa0.y);
            dstA0[2]=wmma::__float_to_tf32(pa0.z); dstA0[3]=wmma::__float_to_tf32(pa0.w);
            dstA1[0]=wmma::__float_to_tf32(pa1.x); dstA1[1]=wmma::__float_to_tf32(pa1.y);
            dstA1[2]=wmma::__float_to_tf32(pa1.z); dstA1[3]=wmma::__float_to_tf32(pa1.w);
            float* dstB0 = Bs[nxt] + bRow * BSTR + bCol;
            float* dstB1 = Bs[nxt] + (bRow + 8) * BSTR + bCol;
            dstB0[0]=wmma::__float_to_tf32(pb0.x); dstB0[1]=wmma::__float_to_tf32(pb0.y);
            dstB0[2]=wmma::__float_to_tf32(pb0.z); dstB0[3]=wmma::__float_to_tf32(pb0.w);
            dstB1[0]=wmma::__float_to_tf32(pb1.x); dstB1[1]=wmma::__float_to_tf32(pb1.y);
            dstB1[2]=wmma::__float_to_tf32(pb1.z); dstB1[3]=wmma::__float_to_tf32(pb1.w);
            __syncthreads();
            cur = nxt;
        }
    }

    // epilogue through smem C tile (aliases load buffers)
    __syncthreads();
    #pragma unroll
    for (int i = 0; i < 4; i++)
        #pragma unroll
        for (int j = 0; j < 2; j++)
            wmma::store_matrix_sync(
                Cs + (warpM * 64 + i * 16) * CSTR + warpN * 32 + j * 16,
                acc[i][j], CSTR, wmma::mem_row_major);
    __syncthreads();

    const int c4 = (tid & 31) << 2;          // col group
    const int r0 = tid >> 5;                 // 8 rows per pass
    float4 bi = *reinterpret_cast<const float4*>(bias + blockN + c4);
    #pragma unroll
    for (int p = 0; p < 16; p++) {
        const int r = r0 + p * 8;
        float4 o = *reinterpret_cast<const float4*>(Cs + r * CSTR + c4);
        o.x += bi.x; o.y += bi.y; o.z += bi.z; o.w += bi.w;
        if (EPI == 1) {
            o.x = fmaxf(o.x, 0.f); o.y = fmaxf(o.y, 0.f);
            o.z = fmaxf(o.z, 0.f); o.w = fmaxf(o.w, 0.f);
        }
        if (EPI == 2) {
            const float* rp = res + (size_t)(blockM + r) * resStride + blockN + c4;
            float4 rv = *reinterpret_cast<const float4*>(rp);
            o.x += rv.x; o.y += rv.y; o.z += rv.z; o.w += rv.w;
        }
        *reinterpret_cast<float4*>(&C[(size_t)(blockM + r) * N + blockN + c4]) = o;
    }
}

// ---------------------------------------------------------------------------
// LayerNorm in place on k and q columns of g_kqv.
// ---------------------------------------------------------------------------
__global__ void ln_kernel(float* __restrict__ kqv,
                          const float* __restrict__ gamma,
                          const float* __restrict__ beta)
{
    const int t   = blockIdx.x;
    const int sel = blockIdx.y;
    float* row = kqv + (size_t)t * D3 + sel * DD;
    const int tid = threadIdx.x;

    float4 v = reinterpret_cast<float4*>(row)[tid];
    float s  = v.x + v.y + v.z + v.w;
    float sq = v.x*v.x + v.y*v.y + v.z*v.z + v.w*v.w;

    #pragma unroll
    for (int o = 16; o; o >>= 1) {
        s  += __shfl_xor_sync(0xffffffffu, s,  o);
        sq += __shfl_xor_sync(0xffffffffu, sq, o);
    }
    __shared__ float rs[4], rq[4];
    if ((tid & 31) == 0) { rs[tid >> 5] = s; rq[tid >> 5] = sq; }
    __syncthreads();
    s  = rs[0] + rs[1] + rs[2] + rs[3];
    sq = rq[0] + rq[1] + rq[2] + rq[3];

    const float mean = s * (1.0f / DD);
    const float var  = sq * (1.0f / DD) - mean * mean;
    const float inv  = rsqrtf(var + 1e-3f);

    float4 g = reinterpret_cast<const float4*>(gamma)[tid];
    float4 b = reinterpret_cast<const float4*>(beta)[tid];
    v.x = (v.x - mean) * inv * g.x + b.x;
    v.y = (v.y - mean) * inv * g.y + b.y;
    v.z = (v.z - mean) * inv * g.z + b.z;
    v.w = (v.w - mean) * inv * g.w + b.w;
    reinterpret_cast<float4*>(row)[tid] = v;
}

// ---------------------------------------------------------------------------
// Tiled sliding-window attention (unchanged from round 2).
// ---------------------------------------------------------------------------
__global__ __launch_bounds__(256, 2)
void attn_tile_kernel(const float* __restrict__ kqv, float* __restrict__ ctx)
{
    extern __shared__ float sm[];
    float* Ksm = sm;
    float* Vsm = sm + KW * KSTR;
    float* Qsm = sm + 2 * KW * KSTR;
    float* Psm = sm;

    const int tid  = threadIdx.x;
    const int tile = blockIdx.x;
    const int h    = blockIdx.y;
    const int b    = blockIdx.z;

    const int t0 = tile * QT;
    int kbase = t0 - WINW;
    if (kbase < 0) kbase = 0;
    if (kbase > SS - KW) kbase = SS - KW;
    const size_t rowBase = (size_t)(b * SS) * D3 + h * HDIM;

    {
        const int r0 = tid >> 4;
        const int c4 = (tid & 15) << 2;
        #pragma unroll
        for (int r = r0; r < KW; r += 16) {
            const float* src = kqv + rowBase + (size_t)(kbase + r) * D3;
            *reinterpret_cast<float4*>(Ksm + r * KSTR + c4) =
                *reinterpret_cast<const float4*>(src + c4);
            *reinterpret_cast<float4*>(Vsm + r * KSTR + c4) =
                *reinterpret_cast<const float4*>(src + 2 * DD + c4);
        }
        #pragma unroll
        for (int r = r0; r < QT; r += 16) {
            const float* src = kqv + rowBase + (size_t)(t0 + r) * D3 + DD;
            *reinterpret_cast<float4*>(Qsm + r * KSTR + c4) =
                *reinterpret_cast<const float4*>(src + c4);
        }
    }
    __syncthreads();

    const int tr = tid >> 4;
    const int tc = tid & 15;

    float acc[2][10];
    #pragma unroll
    for (int i = 0; i < 2; i++)
        #pragma unroll
        for (int j = 0; j < 10; j++) acc[i][j] = 0.f;

    #pragma unroll
    for (int k4 = 0; k4 < HDIM; k4 += 4) {
        float4 qa0 = *reinterpret_cast<const float4*>(Qsm + (tr * 2 + 0) * KSTR + k4);
        float4 qa1 = *reinterpret_cast<const float4*>(Qsm + (tr * 2 + 1) * KSTR + k4);
        #pragma unroll
        for (int j = 0; j < 10; j++) {
            float4 kb = *reinterpret_cast<const float4*>(Ksm + (tc * 10 + j) * KSTR + k4);
            acc[0][j] = fmaf(qa0.x, kb.x, acc[0][j]);
            acc[0][j] = fmaf(qa0.y, kb.y, acc[0][j]);
            acc[0][j] = fmaf(qa0.z, kb.z, acc[0][j]);
            acc[0][j] = fmaf(qa0.w, kb.w, acc[0][j]);
            acc[1][j] = fmaf(qa1.x, kb.x, acc[1][j]);
            acc[1][j] = fmaf(qa1.y, kb.y, acc[1][j]);
            acc[1][j] = fmaf(qa1.z, kb.z, acc[1][j]);
            acc[1][j] = fmaf(qa1.w, kb.w, acc[1][j]);
        }
    }

    float inv[2];
    #pragma unroll
    for (int i = 0; i < 2; i++) {
        const int s = t0 + tr * 2 + i;
        int start = s - WINW;
        if (start < 0) start = 0;
        if (start > SS - SUBW) start = SS - SUBW;
        const int off = start - kbase;

        float mx = -1e30f;
        #pragma unroll
        for (int j = 0; j < 10; j++) {
            const int c = tc * 10 + j;
            float scv = acc[i][j] * 0.125f;
            if (c < off || c >= off + SUBW) scv = -1e30f;
            acc[i][j] = scv;
            mx = fmaxf(mx, scv);
        }
        #pragma unroll
        for (int o = 1; o < 16; o <<= 1)
            mx = fmaxf(mx, __shfl_xor_sync(0xffffffffu, mx, o));

        float sum = 0.f;
        #pragma unroll
        for (int j = 0; j < 10; j++) {
            float e = __expf(acc[i][j] - mx);
            acc[i][j] = e;
            sum += e;
        }
        #pragma unroll
        for (int o = 1; o < 16; o <<= 1)
            sum += __shfl_xor_sync(0xffffffffu, sum, o);
        inv[i] = 1.0f / sum;
    }

    __syncthreads();

    #pragma unroll
    for (int i = 0; i < 2; i++) {
        float* prow = Psm + (tr * 2 + i) * PSTR + tc * 10;
        #pragma unroll
        for (int j = 0; j < 10; j++) prow[j] = acc[i][j] * inv[i];
    }
    __syncthreads();

    const int orr = tid >> 4;
    const int oc4 = (tid & 15) << 2;

    float oacc[2][4];
    #pragma unroll
    for (int i = 0; i < 2; i++)
        #pragma unroll
        for (int j = 0; j < 4; j++) oacc[i][j] = 0.f;

    #pragma unroll 4
    for (int k4 = 0; k4 < KW; k4 += 4) {
        float4 pa0 = *reinterpret_cast<const float4*>(Psm + (orr * 2 + 0) * PSTR + k4);
        float4 pa1 = *reinterpret_cast<const float4*>(Psm + (orr * 2 + 1) * PSTR + k4);
        float4 vb0 = *reinterpret_cast<const float4*>(Vsm + (k4 + 0) * KSTR + oc4);
        float4 vb1 = *reinterpret_cast<const float4*>(Vsm + (k4 + 1) * KSTR + oc4);
        float4 vb2 = *reinterpret_cast<const float4*>(Vsm + (k4 + 2) * KSTR + oc4);
        float4 vb3 = *reinterpret_cast<const float4*>(Vsm + (k4 + 3) * KSTR + oc4);

        oacc[0][0] = fmaf(pa0.x, vb0.x, oacc[0][0]);
        oacc[0][1] = fmaf(pa0.x, vb0.y, oacc[0][1]);
        oacc[0][2] = fmaf(pa0.x, vb0.z, oacc[0][2]);
        oacc[0][3] = fmaf(pa0.x, vb0.w, oacc[0][3]);
        oacc[0][0] = fmaf(pa0.y, vb1.x, oacc[0][0]);
        oacc[0][1] = fmaf(pa0.y, vb1.y, oacc[0][1]);
        oacc[0][2] = fmaf(pa0.y, vb1.z, oacc[0][2]);
        oacc[0][3] = fmaf(pa0.y, vb1.w, oacc[0][3]);
        oacc[0][0] = fmaf(pa0.z, vb2.x, oacc[0][0]);
        oacc[0][1] = fmaf(pa0.z, vb2.y, oacc[0][1]);
        oacc[0][2] = fmaf(pa0.z, vb2.z, oacc[0][2]);
        oacc[0][3] = fmaf(pa0.z, vb2.w, oacc[0][3]);
        oacc[0][0] = fmaf(pa0.w, vb3.x, oacc[0][0]);
        oacc[0][1] = fmaf(pa0.w, vb3.y, oacc[0][1]);
        oacc[0][2] = fmaf(pa0.w, vb3.z, oacc[0][2]);
        oacc[0][3] = fmaf(pa0.w, vb3.w, oacc[0][3]);

        oacc[1][0] = fmaf(pa1.x, vb0.x, oacc[1][0]);
        oacc[1][1] = fmaf(pa1.x, vb0.y, oacc[1][1]);
        oacc[1][2] = fmaf(pa1.x, vb0.z, oacc[1][2]);
        oacc[1][3] = fmaf(pa1.x, vb0.w, oacc[1][3]);
        oacc[1][0] = fmaf(pa1.y, vb1.x, oacc[1][0]);
        oacc[1][1] = fmaf(pa1.y, vb1.y, oacc[1][1]);
        oacc[1][2] = fmaf(pa1.y, vb1.z, oacc[1][2]);
        oacc[1][3] = fmaf(pa1.y, vb1.w, oacc[1][3]);
        oacc[1][0] = fmaf(pa1.z, vb2.x, oacc[1][0]);
        oacc[1][1] = fmaf(pa1.z, vb2.y, oacc[1][1]);
        oacc[1][2] = fmaf(pa1.z, vb2.z, oacc[1][2]);
        oacc[1][3] = fmaf(pa1.z, vb2.w, oacc[1][3]);
        oacc[1][0] = fmaf(pa1.w, vb3.x, oacc[1][0]);
        oacc[1][1] = fmaf(pa1.w, vb3.y, oacc[1][1]);
        oacc[1][2] = fmaf(pa1.w, vb3.z, oacc[1][2]);
        oacc[1][3] = fmaf(pa1.w, vb3.w, oacc[1][3]);
    }

    #pragma unroll
    for (int i = 0; i < 2; i++) {
        float* dst = ctx + (size_t)(b * SS + t0 + orr * 2 + i) * DD + h * HDIM + oc4;
        float4 o;
        o.x = oacc[i][0]; o.y = oacc[i][1]; o.z = oacc[i][2]; o.w = oacc[i][3];
        *reinterpret_cast<float4*>(dst) = o;
    }
}

// ---------------------------------------------------------------------------
extern "C" void kernel_launch(void* const* d_in, const int* in_sizes, int n_in,
                              void* d_out, int out_size)
{
    const float* values   = (const float*)d_in[0];
    const float* W_kqv    = (const float*)d_in[1];
    const float* b_kqv    = (const float*)d_in[2];
    const float* ln_gamma = (const float*)d_in[3];
    const float* ln_beta  = (const float*)d_in[4];
    const float* W_kernel = (const float*)d_in[5];
    const float* b_kernel = (const float*)d_in[6];
    const float* W_proj   = (const float*)d_in[7];
    const float* b_proj   = (const float*)d_in[8];
    float* out = (float*)d_out;

    float *kqv, *ctx, *x1;
    cudaGetSymbolAddress((void**)&kqv, g_kqv);
    cudaGetSymbolAddress((void**)&ctx, g_ctx);
    cudaGetSymbolAddress((void**)&x1,  g_x1);

    const int attnSmem = (2 * KW * KSTR + QT * KSTR) * sizeof(float);
    const int gemmSmem = 128 * CSTR * sizeof(float);  // 67.6 KB (C tile, > load bufs)

    static bool attrSet = false;
    if (!attrSet) {
        cudaFuncSetAttribute(attn_tile_kernel,
                             cudaFuncAttributeMaxDynamicSharedMemorySize, attnSmem);
        cudaFuncSetAttribute(tgemm_k<0>,
                             cudaFuncAttributeMaxDynamicSharedMemorySize, gemmSmem);
        cudaFuncSetAttribute(tgemm_k<1>,
                             cudaFuncAttributeMaxDynamicSharedMemorySize, gemmSmem);
        cudaFuncSetAttribute(tgemm_k<2>,
                             cudaFuncAttributeMaxDynamicSharedMemorySize, gemmSmem);
        attrSet = true;
    }

    // 1) kqv = values @ W_kqv + b_kqv
    tgemm_k<0><<<dim3(D3 / 128, TT / 128), 256, gemmSmem>>>(
        values, W_kqv, b_kqv, nullptr, 0, kqv, TT, D3, DD);

    // 2) LayerNorm q and k in place
    ln_kernel<<<dim3(TT, 2), 128>>>(kqv, ln_gamma, ln_beta);

    // 3) tiled sliding-window attention -> ctx
    attn_tile_kernel<<<dim3(SS / QT, HH, BB), 256, attnSmem>>>(kqv, ctx);

    // 4) x1 = relu(ctx @ W_kernel + b_kernel)
    tgemm_k<1><<<dim3(KSZ / 128, TT / 128), 256, gemmSmem>>>(
        ctx, W_kernel, b_kernel, nullptr, 0, x1, TT, KSZ, DD);

    // 5) out = x1 @ W_proj + b_proj + v
    tgemm_k<2><<<dim3(DD / 128, TT / 128), 256, gemmSmem>>>(
        x1, W_proj, b_proj, kqv + 2 * DD, D3, out, TT, DD, KSZ);
}

// round 6
// speedup vs baseline: 3.8730x; 1.1707x over previous
#include <cuda_runtime.h>
#include <mma.h>
#include <math.h>
#include <stdint.h>

using namespace nvcuda;

// Problem constants
#define BB   2
#define SS   2048
#define HH   8
#define HDIM 64
#define DD   512
#define WINW 64
#define SUBW 129
#define KSZ  2048
#define TT   (BB*SS)          // 4096
#define D3   (3*DD)           // 1536

// Attention tile constants
#define QT   32
#define KW   160
#define KSTR 68
#define PSTR 168

// GEMM tile constants (tf32 wmma + cp.async)
#define BKG   32
#define ASTR  36               // 32 + 4 pad (floats)
#define BSTR  132              // 128 + 4 pad
#define CSTR  132
#define AS_FLOATS (128 * ASTR)           // 4608
#define BS_FLOATS (BKG * BSTR)           // 4224
#define GEMM_SMEM ((2 * AS_FLOATS + 2 * BS_FLOATS) * 4)   // 70656 B

// Scratch (device globals; allocation-free)
__device__ float g_kqv[TT * D3];     // 25 MB
__device__ float g_ctx[TT * DD];     // tf32-rounded ctx
__device__ float g_x1 [TT * KSZ];    // tf32-rounded x1
__device__ float g_va [TT * DD];     // tf32-rounded values
__device__ float g_wq [DD * D3];     // tf32-rounded weights
__device__ float g_wk [DD * KSZ];
__device__ float g_wp [KSZ * DD];

// ---------------------------------------------------------------------------
__device__ __forceinline__ float rtf32(float x) {
    uint32_t u;
    asm("cvt.rna.tf32.f32 %0, %1;" : "=r"(u) : "f"(x));
    return __uint_as_float(u);
}

#define CP_ASYNC16(dst_u32, src_ptr) \
    asm volatile("cp.async.cg.shared.global [%0], [%1], 16;" \
                 :: "r"(dst_u32), "l"(src_ptr))
#define CP_COMMIT()  asm volatile("cp.async.commit_group;")
#define CP_WAIT0()   asm volatile("cp.async.wait_group 0;")
#define CP_WAIT1()   asm volatile("cp.async.wait_group 1;")

// ---------------------------------------------------------------------------
// tf32 wmma GEMM with cp.async double buffering.
// C[M,N] = A[M,K] @ B[K,N] + bias (+ epilogue). A, B pre-rounded to tf32.
// BM=BN=128, BK=32, 256 threads (8 warps), warp tile 64x32.
// EPI: 0 = bias -> f32 ; 1 = bias+relu -> tf32-rounded f32 ; 2 = bias+residual
// ---------------------------------------------------------------------------
template <int EPI>
__global__ __launch_bounds__(256, 2)
void tgemm_k(const float* __restrict__ A, const float* __restrict__ Bm,
             const float* __restrict__ bias,
             const float* __restrict__ res, int resStride,
             float* __restrict__ C, int M, int N, int K)
{
    extern __shared__ float sm[];
    const uint32_t sbase = (uint32_t)__cvta_generic_to_shared(sm);

    const int tid    = threadIdx.x;
    const int warpId = tid >> 5;
    const int warpM  = warpId & 1;      // 0..1 : 64-row half
    const int warpN  = warpId >> 1;     // 0..3 : 32-col block

    const int blockN = blockIdx.x * 128;
    const int blockM = blockIdx.y * 128;

    const int aRow = tid >> 3;               // 0..31 base (4 passes of 32 rows)
    const int aC4  = (tid & 7) << 2;         // 0..28
    const int bRow = tid >> 5;               // 0..7 base (4 passes of 8 rows)
    const int bC4  = (tid & 31) << 2;        // 0..124

    wmma::fragment<wmma::accumulator, 16, 16, 8, float> acc[4][2];
    #pragma unroll
    for (int i = 0; i < 4; i++)
        #pragma unroll
        for (int j = 0; j < 2; j++) wmma::fill_fragment(acc[i][j], 0.f);

    auto loadTile = [&](int k0, int buf) {
        const uint32_t aOff = buf * AS_FLOATS;
        const uint32_t bOff = 2 * AS_FLOATS + buf * BS_FLOATS;
        #pragma unroll
        for (int p = 0; p < 4; p++) {
            const int row = aRow + p * 32;
            CP_ASYNC16(sbase + (aOff + row * ASTR + aC4) * 4,
                       A + (size_t)(blockM + row) * K + k0 + aC4);
        }
        #pragma unroll
        for (int p = 0; p < 4; p++) {
            const int row = bRow + p * 8;
            CP_ASYNC16(sbase + (bOff + row * BSTR + bC4) * 4,
                       Bm + (size_t)(k0 + row) * N + blockN + bC4);
        }
    };

    const int nIter = K / BKG;
    loadTile(0, 0);
    CP_COMMIT();

    for (int i = 0; i < nIter; i++) {
        const int buf = i & 1;
        if (i + 1 < nIter) {
            loadTile((i + 1) * BKG, buf ^ 1);
            CP_COMMIT();
            CP_WAIT1();
        } else {
            CP_WAIT0();
        }
        __syncthreads();

        const float* As = sm + buf * AS_FLOATS;
        const float* Bs = sm + 2 * AS_FLOATS + buf * BS_FLOATS;
        #pragma unroll
        for (int kk = 0; kk < BKG; kk += 8) {
            wmma::fragment<wmma::matrix_a, 16, 16, 8, wmma::precision::tf32, wmma::row_major> af[4];
            wmma::fragment<wmma::matrix_b, 16, 16, 8, wmma::precision::tf32, wmma::row_major> bf[2];
            #pragma unroll
            for (int ii = 0; ii < 4; ii++)
                wmma::load_matrix_sync(af[ii],
                    As + (warpM * 64 + ii * 16) * ASTR + kk, ASTR);
            #pragma unroll
            for (int j = 0; j < 2; j++)
                wmma::load_matrix_sync(bf[j],
                    Bs + kk * BSTR + warpN * 32 + j * 16, BSTR);
            #pragma unroll
            for (int ii = 0; ii < 4; ii++)
                #pragma unroll
                for (int j = 0; j < 2; j++)
                    wmma::mma_sync(acc[ii][j], af[ii], bf[j], acc[ii][j]);
        }
        __syncthreads();
    }

    // epilogue: two 64-row chunks staged through smem (aliases load buffers)
    const int tr8 = tid >> 5;                // 0..7
    const int tc4 = (tid & 31) << 2;         // 0..124
    float4 bi = *reinterpret_cast<const float4*>(bias + blockN + tc4);

    #pragma unroll
    for (int half = 0; half < 2; half++) {
        __syncthreads();
        if (warpM == half) {
            #pragma unroll
            for (int ii = 0; ii < 4; ii++)
                #pragma unroll
                for (int j = 0; j < 2; j++)
                    wmma::store_matrix_sync(
                        sm + (ii * 16) * CSTR + warpN * 32 + j * 16,
                        acc[ii][j], CSTR, wmma::mem_row_major);
        }
        __syncthreads();
        #pragma unroll
        for (int p = 0; p < 8; p++) {
            const int r = p * 8 + tr8;
            const int grow = blockM + half * 64 + r;
            float4 o = *reinterpret_cast<const float4*>(sm + r * CSTR + tc4);
            o.x += bi.x; o.y += bi.y; o.z += bi.z; o.w += bi.w;
            if (EPI == 1) {
                o.x = rtf32(fmaxf(o.x, 0.f)); o.y = rtf32(fmaxf(o.y, 0.f));
                o.z = rtf32(fmaxf(o.z, 0.f)); o.w = rtf32(fmaxf(o.w, 0.f));
            }
            if (EPI == 2) {
                float4 rv = *reinterpret_cast<const float4*>(
                    res + (size_t)grow * resStride + blockN + tc4);
                o.x += rv.x; o.y += rv.y; o.z += rv.z; o.w += rv.w;
            }
            *reinterpret_cast<float4*>(&C[(size_t)grow * N + blockN + tc4]) = o;
        }
    }
}

// ---------------------------------------------------------------------------
// tf32 rounding pre-pass (vectorized copy)
// ---------------------------------------------------------------------------
__global__ void tf32_round_k(const float* __restrict__ in, float* __restrict__ out)
{
    const int i = blockIdx.x * blockDim.x + threadIdx.x;
    float4 v = reinterpret_cast<const float4*>(in)[i];
    v.x = rtf32(v.x); v.y = rtf32(v.y); v.z = rtf32(v.z); v.w = rtf32(v.w);
    reinterpret_cast<float4*>(out)[i] = v;
}

// ---------------------------------------------------------------------------
// LayerNorm in place on k and q columns of g_kqv.
// ---------------------------------------------------------------------------
__global__ void ln_kernel(float* __restrict__ kqv,
                          const float* __restrict__ gamma,
                          const float* __restrict__ beta)
{
    const int t   = blockIdx.x;
    const int sel = blockIdx.y;
    float* row = kqv + (size_t)t * D3 + sel * DD;
    const int tid = threadIdx.x;

    float4 v = reinterpret_cast<float4*>(row)[tid];
    float s  = v.x + v.y + v.z + v.w;
    float sq = v.x*v.x + v.y*v.y + v.z*v.z + v.w*v.w;

    #pragma unroll
    for (int o = 16; o; o >>= 1) {
        s  += __shfl_xor_sync(0xffffffffu, s,  o);
        sq += __shfl_xor_sync(0xffffffffu, sq, o);
    }
    __shared__ float rs[4], rq[4];
    if ((tid & 31) == 0) { rs[tid >> 5] = s; rq[tid >> 5] = sq; }
    __syncthreads();
    s  = rs[0] + rs[1] + rs[2] + rs[3];
    sq = rq[0] + rq[1] + rq[2] + rq[3];

    const float mean = s * (1.0f / DD);
    const float var  = sq * (1.0f / DD) - mean * mean;
    const float inv  = rsqrtf(var + 1e-3f);

    float4 g = reinterpret_cast<const float4*>(gamma)[tid];
    float4 b = reinterpret_cast<const float4*>(beta)[tid];
    v.x = (v.x - mean) * inv * g.x + b.x;
    v.y = (v.y - mean) * inv * g.y + b.y;
    v.z = (v.z - mean) * inv * g.z + b.z;
    v.w = (v.w - mean) * inv * g.w + b.w;
    reinterpret_cast<float4*>(row)[tid] = v;
}

// ---------------------------------------------------------------------------
// Tiled sliding-window attention; outputs ctx tf32-rounded (for GEMM2).
// ---------------------------------------------------------------------------
__global__ __launch_bounds__(256, 2)
void attn_tile_kernel(const float* __restrict__ kqv, float* __restrict__ ctx)
{
    extern __shared__ float sm[];
    float* Ksm = sm;
    float* Vsm = sm + KW * KSTR;
    float* Qsm = sm + 2 * KW * KSTR;
    float* Psm = sm;

    const int tid  = threadIdx.x;
    const int tile = blockIdx.x;
    const int h    = blockIdx.y;
    const int b    = blockIdx.z;

    const int t0 = tile * QT;
    int kbase = t0 - WINW;
    if (kbase < 0) kbase = 0;
    if (kbase > SS - KW) kbase = SS - KW;
    const size_t rowBase = (size_t)(b * SS) * D3 + h * HDIM;

    {
        const int r0 = tid >> 4;
        const int c4 = (tid & 15) << 2;
        #pragma unroll
        for (int r = r0; r < KW; r += 16) {
            const float* src = kqv + rowBase + (size_t)(kbase + r) * D3;
            *reinterpret_cast<float4*>(Ksm + r * KSTR + c4) =
                *reinterpret_cast<const float4*>(src + c4);
            *reinterpret_cast<float4*>(Vsm + r * KSTR + c4) =
                *reinterpret_cast<const float4*>(src + 2 * DD + c4);
        }
        #pragma unroll
        for (int r = r0; r < QT; r += 16) {
            const float* src = kqv + rowBase + (size_t)(t0 + r) * D3 + DD;
            *reinterpret_cast<float4*>(Qsm + r * KSTR + c4) =
                *reinterpret_cast<const float4*>(src + c4);
        }
    }
    __syncthreads();

    const int tr = tid >> 4;
    const int tc = tid & 15;

    float acc[2][10];
    #pragma unroll
    for (int i = 0; i < 2; i++)
        #pragma unroll
        for (int j = 0; j < 10; j++) acc[i][j] = 0.f;

    #pragma unroll
    for (int k4 = 0; k4 < HDIM; k4 += 4) {
        float4 qa0 = *reinterpret_cast<const float4*>(Qsm + (tr * 2 + 0) * KSTR + k4);
        float4 qa1 = *reinterpret_cast<const float4*>(Qsm + (tr * 2 + 1) * KSTR + k4);
        #pragma unroll
        for (int j = 0; j < 10; j++) {
            float4 kb = *reinterpret_cast<const float4*>(Ksm + (tc * 10 + j) * KSTR + k4);
            acc[0][j] = fmaf(qa0.x, kb.x, acc[0][j]);
            acc[0][j] = fmaf(qa0.y, kb.y, acc[0][j]);
            acc[0][j] = fmaf(qa0.z, kb.z, acc[0][j]);
            acc[0][j] = fmaf(qa0.w, kb.w, acc[0][j]);
            acc[1][j] = fmaf(qa1.x, kb.x, acc[1][j]);
            acc[1][j] = fmaf(qa1.y, kb.y, acc[1][j]);
            acc[1][j] = fmaf(qa1.z, kb.z, acc[1][j]);
            acc[1][j] = fmaf(qa1.w, kb.w, acc[1][j]);
        }
    }

    float inv[2];
    #pragma unroll
    for (int i = 0; i < 2; i++) {
        const int s = t0 + tr * 2 + i;
        int start = s - WINW;
        if (start < 0) start = 0;
        if (start > SS - SUBW) start = SS - SUBW;
        const int off = start - kbase;

        float mx = -1e30f;
        #pragma unroll
        for (int j = 0; j < 10; j++) {
            const int c = tc * 10 + j;
            float scv = acc[i][j] * 0.125f;
            if (c < off || c >= off + SUBW) scv = -1e30f;
            acc[i][j] = scv;
            mx = fmaxf(mx, scv);
        }
        #pragma unroll
        for (int o = 1; o < 16; o <<= 1)
            mx = fmaxf(mx, __shfl_xor_sync(0xffffffffu, mx, o));

        float sum = 0.f;
        #pragma unroll
        for (int j = 0; j < 10; j++) {
            float e = __expf(acc[i][j] - mx);
            acc[i][j] = e;
            sum += e;
        }
        #pragma unroll
        for (int o = 1; o < 16; o <<= 1)
            sum += __shfl_xor_sync(0xffffffffu, sum, o);
        inv[i] = 1.0f / sum;
    }

    __syncthreads();

    #pragma unroll
    for (int i = 0; i < 2; i++) {
        float* prow = Psm + (tr * 2 + i) * PSTR + tc * 10;
        #pragma unroll
        for (int j = 0; j < 10; j++) prow[j] = acc[i][j] * inv[i];
    }
    __syncthreads();

    const int orr = tid >> 4;
    const int oc4 = (tid & 15) << 2;

    float oacc[2][4];
    #pragma unroll
    for (int i = 0; i < 2; i++)
        #pragma unroll
        for (int j = 0; j < 4; j++) oacc[i][j] = 0.f;

    #pragma unroll 4
    for (int k4 = 0; k4 < KW; k4 += 4) {
        float4 pa0 = *reinterpret_cast<const float4*>(Psm + (orr * 2 + 0) * PSTR + k4);
        float4 pa1 = *reinterpret_cast<const float4*>(Psm + (orr * 2 + 1) * PSTR + k4);
        float4 vb0 = *reinterpret_cast<const float4*>(Vsm + (k4 + 0) * KSTR + oc4);
        float4 vb1 = *reinterpret_cast<const float4*>(Vsm + (k4 + 1) * KSTR + oc4);
        float4 vb2 = *reinterpret_cast<const float4*>(Vsm + (k4 + 2) * KSTR + oc4);
        float4 vb3 = *reinterpret_cast<const float4*>(Vsm + (k4 + 3) * KSTR + oc4);

        oacc[0][0] = fmaf(pa0.x, vb0.x, oacc[0][0]);
        oacc[0][1] = fmaf(pa0.x, vb0.y, oacc[0][1]);
        oacc[0][2] = fmaf(pa0.x, vb0.z, oacc[0][2]);
        oacc[0][3] = fmaf(pa0.x, vb0.w, oacc[0][3]);
        oacc[0][0] = fmaf(pa0.y, vb1.x, oacc[0][0]);
        oacc[0][1] = fmaf(pa0.y, vb1.y, oacc[0][1]);
        oacc[0][2] = fmaf(pa0.y, vb1.z, oacc[0][2]);
        oacc[0][3] = fmaf(pa0.y, vb1.w, oacc[0][3]);
        oacc[0][0] = fmaf(pa0.z, vb2.x, oacc[0][0]);
        oacc[0][1] = fmaf(pa0.z, vb2.y, oacc[0][1]);
        oacc[0][2] = fmaf(pa0.z, vb2.z, oacc[0][2]);
        oacc[0][3] = fmaf(pa0.z, vb2.w, oacc[0][3]);
        oacc[0][0] = fmaf(pa0.w, vb3.x, oacc[0][0]);
        oacc[0][1] = fmaf(pa0.w, vb3.y, oacc[0][1]);
        oacc[0][2] = fmaf(pa0.w, vb3.z, oacc[0][2]);
        oacc[0][3] = fmaf(pa0.w, vb3.w, oacc[0][3]);

        oacc[1][0] = fmaf(pa1.x, vb0.x, oacc[1][0]);
        oacc[1][1] = fmaf(pa1.x, vb0.y, oacc[1][1]);
        oacc[1][2] = fmaf(pa1.x, vb0.z, oacc[1][2]);
        oacc[1][3] = fmaf(pa1.x, vb0.w, oacc[1][3]);
        oacc[1][0] = fmaf(pa1.y, vb1.x, oacc[1][0]);
        oacc[1][1] = fmaf(pa1.y, vb1.y, oacc[1][1]);
        oacc[1][2] = fmaf(pa1.y, vb1.z, oacc[1][2]);
        oacc[1][3] = fmaf(pa1.y, vb1.w, oacc[1][3]);
        oacc[1][0] = fmaf(pa1.z, vb2.x, oacc[1][0]);
        oacc[1][1] = fmaf(pa1.z, vb2.y, oacc[1][1]);
        oacc[1][2] = fmaf(pa1.z, vb2.z, oacc[1][2]);
        oacc[1][3] = fmaf(pa1.z, vb2.w, oacc[1][3]);
        oacc[1][0] = fmaf(pa1.w, vb3.x, oacc[1][0]);
        oacc[1][1] = fmaf(pa1.w, vb3.y, oacc[1][1]);
        oacc[1][2] = fmaf(pa1.w, vb3.z, oacc[1][2]);
        oacc[1][3] = fmaf(pa1.w, vb3.w, oacc[1][3]);
    }

    #pragma unroll
    for (int i = 0; i < 2; i++) {
        float* dst = ctx + (size_t)(b * SS + t0 + orr * 2 + i) * DD + h * HDIM + oc4;
        float4 o;
        o.x = rtf32(oacc[i][0]); o.y = rtf32(oacc[i][1]);
        o.z = rtf32(oacc[i][2]); o.w = rtf32(oacc[i][3]);
        *reinterpret_cast<float4*>(dst) = o;
    }
}

// ---------------------------------------------------------------------------
extern "C" void kernel_launch(void* const* d_in, const int* in_sizes, int n_in,
                              void* d_out, int out_size)
{
    const float* values   = (const float*)d_in[0];
    const float* W_kqv    = (const float*)d_in[1];
    const float* b_kqv    = (const float*)d_in[2];
    const float* ln_gamma = (const float*)d_in[3];
    const float* ln_beta  = (const float*)d_in[4];
    const float* W_kernel = (const float*)d_in[5];
    const float* b_kernel = (const float*)d_in[6];
    const float* W_proj   = (const float*)d_in[7];
    const float* b_proj   = (const float*)d_in[8];
    float* out = (float*)d_out;

    float *kqv, *ctx, *x1, *va, *wq, *wk, *wp;
    cudaGetSymbolAddress((void**)&kqv, g_kqv);
    cudaGetSymbolAddress((void**)&ctx, g_ctx);
    cudaGetSymbolAddress((void**)&x1,  g_x1);
    cudaGetSymbolAddress((void**)&va,  g_va);
    cudaGetSymbolAddress((void**)&wq,  g_wq);
    cudaGetSymbolAddress((void**)&wk,  g_wk);
    cudaGetSymbolAddress((void**)&wp,  g_wp);

    const int attnSmem = (2 * KW * KSTR + QT * KSTR) * sizeof(float);

    static bool attrSet = false;
    if (!attrSet) {
        cudaFuncSetAttribute(attn_tile_kernel,
                             cudaFuncAttributeMaxDynamicSharedMemorySize, attnSmem);
        cudaFuncSetAttribute(tgemm_k<0>,
                             cudaFuncAttributeMaxDynamicSharedMemorySize, GEMM_SMEM);
        cudaFuncSetAttribute(tgemm_k<1>,
                             cudaFuncAttributeMaxDynamicSharedMemorySize, GEMM_SMEM);
        cudaFuncSetAttribute(tgemm_k<2>,
                             cudaFuncAttributeMaxDynamicSharedMemorySize, GEMM_SMEM);
        attrSet = true;
    }

    // 0) tf32 rounding pre-passes
    tf32_round_k<<<(TT * DD / 4) / 256, 256>>>(values, va);
    tf32_round_k<<<(DD * D3 / 4) / 256, 256>>>(W_kqv, wq);
    tf32_round_k<<<(DD * KSZ / 4) / 256, 256>>>(W_kernel, wk);
    tf32_round_k<<<(KSZ * DD / 4) / 256, 256>>>(W_proj, wp);

    // 1) kqv = values @ W_kqv + b_kqv
    tgemm_k<0><<<dim3(D3 / 128, TT / 128), 256, GEMM_SMEM>>>(
        va, wq, b_kqv, nullptr, 0, kqv, TT, D3, DD);

    // 2) LayerNorm q and k in place
    ln_kernel<<<dim3(TT, 2), 128>>>(kqv, ln_gamma, ln_beta);

    // 3) attention -> ctx (tf32-rounded)
    attn_tile_kernel<<<dim3(SS / QT, HH, BB), 256, attnSmem>>>(kqv, ctx);

    // 4) x1 = relu(ctx @ W_kernel + b_kernel) (tf32-rounded out)
    tgemm_k<1><<<dim3(KSZ / 128, TT / 128), 256, GEMM_SMEM>>>(
        ctx, wk, b_kernel, nullptr, 0, x1, TT, KSZ, DD);

    // 5) out = x1 @ W_proj + b_proj + v
    tgemm_k<2><<<dim3(DD / 128, TT / 128), 256, GEMM_SMEM>>>(
        x1, wp, b_proj, kqv + 2 * DD, D3, out, TT, DD, KSZ);
}

// round 7
// speedup vs baseline: 4.0798x; 1.0534x over previous
#include <cuda_runtime.h>
#include <mma.h>
#include <math.h>
#include <stdint.h>

using namespace nvcuda;

// Problem constants
#define BB   2
#define SS   2048
#define HH   8
#define HDIM 64
#define DD   512
#define WINW 64
#define SUBW 129
#define KSZ  2048
#define TT   (BB*SS)          // 4096
#define D3   (3*DD)           // 1536

// Attention tile constants
#define QT   32
#define KW   160
#define KSTR 68
#define PSTR 168

// GEMM tile constants (tf32 wmma + cp.async)
#define BKG   32
#define ASTR  36
#define BSTR  132
#define CSTR  132
#define AS_FLOATS (128 * ASTR)
#define BS_FLOATS (BKG * BSTR)
#define GEMM_SMEM ((2 * AS_FLOATS + 2 * BS_FLOATS) * 4)   // 70656 B

// Scratch (device globals; allocation-free)
__device__ float g_kqv[TT * D3];
__device__ float g_ctx[TT * DD];
__device__ float g_x1 [TT * KSZ];
__device__ float g_va [TT * DD];
__device__ float g_wq [DD * D3];
__device__ float g_wk [DD * KSZ];
__device__ float g_wp [KSZ * DD];

// ---------------------------------------------------------------------------
__device__ __forceinline__ float rtf32(float x) {
    uint32_t u;
    asm("cvt.rna.tf32.f32 %0, %1;" : "=r"(u) : "f"(x));
    return __uint_as_float(u);
}

#define CP_ASYNC16(dst_u32, src_ptr) \
    asm volatile("cp.async.cg.shared.global [%0], [%1], 16;" \
                 :: "r"(dst_u32), "l"(src_ptr))
#define CP_COMMIT()  asm volatile("cp.async.commit_group;")
#define CP_WAIT0()   asm volatile("cp.async.wait_group 0;")
#define CP_WAIT1()   asm volatile("cp.async.wait_group 1;")

// ---------------------------------------------------------------------------
// tf32 wmma GEMM with cp.async double buffering (unchanged from round 6).
// ---------------------------------------------------------------------------
template <int EPI>
__global__ __launch_bounds__(256, 2)
void tgemm_k(const float* __restrict__ A, const float* __restrict__ Bm,
             const float* __restrict__ bias,
             const float* __restrict__ res, int resStride,
             float* __restrict__ C, int M, int N, int K)
{
    extern __shared__ float sm[];
    const uint32_t sbase = (uint32_t)__cvta_generic_to_shared(sm);

    const int tid    = threadIdx.x;
    const int warpId = tid >> 5;
    const int warpM  = warpId & 1;
    const int warpN  = warpId >> 1;

    const int blockN = blockIdx.x * 128;
    const int blockM = blockIdx.y * 128;

    const int aRow = tid >> 3;
    const int aC4  = (tid & 7) << 2;
    const int bRow = tid >> 5;
    const int bC4  = (tid & 31) << 2;

    wmma::fragment<wmma::accumulator, 16, 16, 8, float> acc[4][2];
    #pragma unroll
    for (int i = 0; i < 4; i++)
        #pragma unroll
        for (int j = 0; j < 2; j++) wmma::fill_fragment(acc[i][j], 0.f);

    auto loadTile = [&](int k0, int buf) {
        const uint32_t aOff = buf * AS_FLOATS;
        const uint32_t bOff = 2 * AS_FLOATS + buf * BS_FLOATS;
        #pragma unroll
        for (int p = 0; p < 4; p++) {
            const int row = aRow + p * 32;
            CP_ASYNC16(sbase + (aOff + row * ASTR + aC4) * 4,
                       A + (size_t)(blockM + row) * K + k0 + aC4);
        }
        #pragma unroll
        for (int p = 0; p < 4; p++) {
            const int row = bRow + p * 8;
            CP_ASYNC16(sbase + (bOff + row * BSTR + bC4) * 4,
                       Bm + (size_t)(k0 + row) * N + blockN + bC4);
        }
    };

    const int nIter = K / BKG;
    loadTile(0, 0);
    CP_COMMIT();

    for (int i = 0; i < nIter; i++) {
        const int buf = i & 1;
        if (i + 1 < nIter) {
            loadTile((i + 1) * BKG, buf ^ 1);
            CP_COMMIT();
            CP_WAIT1();
        } else {
            CP_WAIT0();
        }
        __syncthreads();

        const float* As = sm + buf * AS_FLOATS;
        const float* Bs = sm + 2 * AS_FLOATS + buf * BS_FLOATS;
        #pragma unroll
        for (int kk = 0; kk < BKG; kk += 8) {
            wmma::fragment<wmma::matrix_a, 16, 16, 8, wmma::precision::tf32, wmma::row_major> af[4];
            wmma::fragment<wmma::matrix_b, 16, 16, 8, wmma::precision::tf32, wmma::row_major> bf[2];
            #pragma unroll
            for (int ii = 0; ii < 4; ii++)
                wmma::load_matrix_sync(af[ii],
                    As + (warpM * 64 + ii * 16) * ASTR + kk, ASTR);
            #pragma unroll
            for (int j = 0; j < 2; j++)
                wmma::load_matrix_sync(bf[j],
                    Bs + kk * BSTR + warpN * 32 + j * 16, BSTR);
            #pragma unroll
            for (int ii = 0; ii < 4; ii++)
                #pragma unroll
                for (int j = 0; j < 2; j++)
                    wmma::mma_sync(acc[ii][j], af[ii], bf[j], acc[ii][j]);
        }
        __syncthreads();
    }

    const int tr8 = tid >> 5;
    const int tc4 = (tid & 31) << 2;
    float4 bi = *reinterpret_cast<const float4*>(bias + blockN + tc4);

    #pragma unroll
    for (int half = 0; half < 2; half++) {
        __syncthreads();
        if (warpM == half) {
            #pragma unroll
            for (int ii = 0; ii < 4; ii++)
                #pragma unroll
                for (int j = 0; j < 2; j++)
                    wmma::store_matrix_sync(
                        sm + (ii * 16) * CSTR + warpN * 32 + j * 16,
                        acc[ii][j], CSTR, wmma::mem_row_major);
        }
        __syncthreads();
        #pragma unroll
        for (int p = 0; p < 8; p++) {
            const int r = p * 8 + tr8;
            const int grow = blockM + half * 64 + r;
            float4 o = *reinterpret_cast<const float4*>(sm + r * CSTR + tc4);
            o.x += bi.x; o.y += bi.y; o.z += bi.z; o.w += bi.w;
            if (EPI == 1) {
                o.x = rtf32(fmaxf(o.x, 0.f)); o.y = rtf32(fmaxf(o.y, 0.f));
                o.z = rtf32(fmaxf(o.z, 0.f)); o.w = rtf32(fmaxf(o.w, 0.f));
            }
            if (EPI == 2) {
                float4 rv = *reinterpret_cast<const float4*>(
                    res + (size_t)grow * resStride + blockN + tc4);
                o.x += rv.x; o.y += rv.y; o.z += rv.z; o.w += rv.w;
            }
            *reinterpret_cast<float4*>(&C[(size_t)grow * N + blockN + tc4]) = o;
        }
    }
}

// ---------------------------------------------------------------------------
// Fused tf32 rounding of all four source tensors in one launch.
// Ranges (in float4 units): va 524288, wq 196608, wk 262144, wp 262144.
// ---------------------------------------------------------------------------
#define R_VA 524288
#define R_WQ (R_VA + 196608)
#define R_WK (R_WQ + 262144)
#define R_WP (R_WK + 262144)

__global__ void tf32_round_all(const float* __restrict__ values,
                               const float* __restrict__ Wq,
                               const float* __restrict__ Wk,
                               const float* __restrict__ Wp,
                               float* __restrict__ va, float* __restrict__ wq,
                               float* __restrict__ wk, float* __restrict__ wp)
{
    const int i = blockIdx.x * blockDim.x + threadIdx.x;
    const float4* src; float4* dst; int off;
    if (i < R_VA)      { src = (const float4*)values; dst = (float4*)va; off = i; }
    else if (i < R_WQ) { src = (const float4*)Wq;     dst = (float4*)wq; off = i - R_VA; }
    else if (i < R_WK) { src = (const float4*)Wk;     dst = (float4*)wk; off = i - R_WQ; }
    else               { src = (const float4*)Wp;     dst = (float4*)wp; off = i - R_WK; }
    float4 v = src[off];
    v.x = rtf32(v.x); v.y = rtf32(v.y); v.z = rtf32(v.z); v.w = rtf32(v.w);
    dst[off] = v;
}

// ---------------------------------------------------------------------------
// LayerNorm in place on k and q columns of g_kqv.
// ---------------------------------------------------------------------------
__global__ void ln_kernel(float* __restrict__ kqv,
                          const float* __restrict__ gamma,
                          const float* __restrict__ beta)
{
    const int t   = blockIdx.x;
    const int sel = blockIdx.y;
    float* row = kqv + (size_t)t * D3 + sel * DD;
    const int tid = threadIdx.x;

    float4 v = reinterpret_cast<float4*>(row)[tid];
    float s  = v.x + v.y + v.z + v.w;
    float sq = v.x*v.x + v.y*v.y + v.z*v.z + v.w*v.w;

    #pragma unroll
    for (int o = 16; o; o >>= 1) {
        s  += __shfl_xor_sync(0xffffffffu, s,  o);
        sq += __shfl_xor_sync(0xffffffffu, sq, o);
    }
    __shared__ float rs[4], rq[4];
    if ((tid & 31) == 0) { rs[tid >> 5] = s; rq[tid >> 5] = sq; }
    __syncthreads();
    s  = rs[0] + rs[1] + rs[2] + rs[3];
    sq = rq[0] + rq[1] + rq[2] + rq[3];

    const float mean = s * (1.0f / DD);
    const float var  = sq * (1.0f / DD) - mean * mean;
    const float inv  = rsqrtf(var + 1e-3f);

    float4 g = reinterpret_cast<const float4*>(gamma)[tid];
    float4 b = reinterpret_cast<const float4*>(beta)[tid];
    v.x = (v.x - mean) * inv * g.x + b.x;
    v.y = (v.y - mean) * inv * g.y + b.y;
    v.z = (v.z - mean) * inv * g.z + b.z;
    v.w = (v.w - mean) * inv * g.w + b.w;
    reinterpret_cast<float4*>(row)[tid] = v;
}

// ---------------------------------------------------------------------------
// Tiled sliding-window attention, v2: 128 threads, 4x10 score tile with
// stride-16 column mapping (conflict-free K loads), 4x4 PV tile.
// ---------------------------------------------------------------------------
__global__ __launch_bounds__(128, 2)
void attn_tile_kernel(const float* __restrict__ kqv, float* __restrict__ ctx)
{
    extern __shared__ float sm[];
    float* Ksm = sm;                         // [KW][KSTR]
    float* Vsm = sm + KW * KSTR;             // [KW][KSTR]
    float* Qsm = sm + 2 * KW * KSTR;         // [QT][KSTR]
    float* Psm = sm;                         // [QT][PSTR] (overlaps Ksm)

    const int tid  = threadIdx.x;
    const int tile = blockIdx.x;
    const int h    = blockIdx.y;
    const int b    = blockIdx.z;

    const int t0 = tile * QT;
    int kbase = t0 - WINW;
    if (kbase < 0) kbase = 0;
    if (kbase > SS - KW) kbase = SS - KW;
    const size_t rowBase = (size_t)(b * SS) * D3 + h * HDIM;

    // ---- stage K, V, Q (coalesced float4, 128 threads: 8 rows/pass) ----
    {
        const int r0 = tid >> 4;             // 0..7
        const int c4 = (tid & 15) << 2;
        #pragma unroll
        for (int r = r0; r < KW; r += 8) {
            const float* src = kqv + rowBase + (size_t)(kbase + r) * D3;
            *reinterpret_cast<float4*>(Ksm + r * KSTR + c4) =
                *reinterpret_cast<const float4*>(src + c4);
            *reinterpret_cast<float4*>(Vsm + r * KSTR + c4) =
                *reinterpret_cast<const float4*>(src + 2 * DD + c4);
        }
        #pragma unroll
        for (int r = r0; r < QT; r += 8) {
            const float* src = kqv + rowBase + (size_t)(t0 + r) * D3 + DD;
            *reinterpret_cast<float4*>(Qsm + r * KSTR + c4) =
                *reinterpret_cast<const float4*>(src + c4);
        }
    }
    __syncthreads();

    // ---- scores: thread (tr 0..7, tc 0..15): q-rows {4tr..4tr+3},
    //      k-cols {tc + 16m, m=0..9}  (stride-16: conflict-free LDS) ----
    const int tr = tid >> 4;                 // 0..7
    const int tc = tid & 15;                 // 0..15

    float acc[4][10];
    #pragma unroll
    for (int i = 0; i < 4; i++)
        #pragma unroll
        for (int j = 0; j < 10; j++) acc[i][j] = 0.f;

    #pragma unroll
    for (int k4 = 0; k4 < HDIM; k4 += 4) {
        float4 qa[4];
        #pragma unroll
        for (int i = 0; i < 4; i++)
            qa[i] = *reinterpret_cast<const float4*>(Qsm + (tr * 4 + i) * KSTR + k4);
        #pragma unroll
        for (int j = 0; j < 10; j++) {
            float4 kb = *reinterpret_cast<const float4*>(Ksm + (tc + 16 * j) * KSTR + k4);
            #pragma unroll
            for (int i = 0; i < 4; i++) {
                acc[i][j] = fmaf(qa[i].x, kb.x, acc[i][j]);
                acc[i][j] = fmaf(qa[i].y, kb.y, acc[i][j]);
                acc[i][j] = fmaf(qa[i].z, kb.z, acc[i][j]);
                acc[i][j] = fmaf(qa[i].w, kb.w, acc[i][j]);
            }
        }
    }

    // ---- mask + softmax (per row; 16 lanes share a row) ----
    float inv[4];
    #pragma unroll
    for (int i = 0; i < 4; i++) {
        const int s = t0 + tr * 4 + i;
        int start = s - WINW;
        if (start < 0) start = 0;
        if (start > SS - SUBW) start = SS - SUBW;
        const int off = start - kbase;       // valid cols: [off, off+SUBW)

        float mx = -1e30f;
        #pragma unroll
        for (int j = 0; j < 10; j++) {
            const int c = tc + 16 * j;
            float scv = acc[i][j] * 0.125f;
            if (c < off || c >= off + SUBW) scv = -1e30f;
            acc[i][j] = scv;
            mx = fmaxf(mx, scv);
        }
        #pragma unroll
        for (int o = 1; o < 16; o <<= 1)
            mx = fmaxf(mx, __shfl_xor_sync(0xffffffffu, mx, o));

        float sum = 0.f;
        #pragma unroll
        for (int j = 0; j < 10; j++) {
            float e = __expf(acc[i][j] - mx);
            acc[i][j] = e;
            sum += e;
        }
        #pragma unroll
        for (int o = 1; o < 16; o <<= 1)
            sum += __shfl_xor_sync(0xffffffffu, sum, o);
        inv[i] = 1.0f / sum;
    }

    __syncthreads();   // done reading Ksm before P overwrites it

    #pragma unroll
    for (int i = 0; i < 4; i++) {
        float* prow = Psm + (tr * 4 + i) * PSTR;
        #pragma unroll
        for (int j = 0; j < 10; j++) prow[tc + 16 * j] = acc[i][j] * inv[i];
    }
    __syncthreads();

    // ---- ctx = P(32x160) @ V(160x64): thread = 4 rows x 4 cols ----
    const int orr = tid >> 4;                // rows {4orr..4orr+3}
    const int oc4 = (tid & 15) << 2;

    float oacc[4][4];
    #pragma unroll
    for (int i = 0; i < 4; i++)
        #pragma unroll
        for (int j = 0; j < 4; j++) oacc[i][j] = 0.f;

    #pragma unroll 5
    for (int k4 = 0; k4 < KW; k4 += 4) {
        float4 pa[4];
        #pragma unroll
        for (int i = 0; i < 4; i++)
            pa[i] = *reinterpret_cast<const float4*>(Psm + (orr * 4 + i) * PSTR + k4);
        float4 vb[4];
        #pragma unroll
        for (int q = 0; q < 4; q++)
            vb[q] = *reinterpret_cast<const float4*>(Vsm + (k4 + q) * KSTR + oc4);

        #pragma unroll
        for (int i = 0; i < 4; i++) {
            oacc[i][0] = fmaf(pa[i].x, vb[0].x, oacc[i][0]);
            oacc[i][1] = fmaf(pa[i].x, vb[0].y, oacc[i][1]);
            oacc[i][2] = fmaf(pa[i].x, vb[0].z, oacc[i][2]);
            oacc[i][3] = fmaf(pa[i].x, vb[0].w, oacc[i][3]);
            oacc[i][0] = fmaf(pa[i].y, vb[1].x, oacc[i][0]);
            oacc[i][1] = fmaf(pa[i].y, vb[1].y, oacc[i][1]);
            oacc[i][2] = fmaf(pa[i].y, vb[1].z, oacc[i][2]);
            oacc[i][3] = fmaf(pa[i].y, vb[1].w, oacc[i][3]);
            oacc[i][0] = fmaf(pa[i].z, vb[2].x, oacc[i][0]);
            oacc[i][1] = fmaf(pa[i].z, vb[2].y, oacc[i][1]);
            oacc[i][2] = fmaf(pa[i].z, vb[2].z, oacc[i][2]);
            oacc[i][3] = fmaf(pa[i].z, vb[2].w, oacc[i][3]);
            oacc[i][0] = fmaf(pa[i].w, vb[3].x, oacc[i][0]);
            oacc[i][1] = fmaf(pa[i].w, vb[3].y, oacc[i][1]);
            oacc[i][2] = fmaf(pa[i].w, vb[3].z, oacc[i][2]);
            oacc[i][3] = fmaf(pa[i].w, vb[3].w, oacc[i][3]);
        }
    }

    #pragma unroll
    for (int i = 0; i < 4; i++) {
        float* dst = ctx + (size_t)(b * SS + t0 + orr * 4 + i) * DD + h * HDIM + oc4;
        float4 o;
        o.x = rtf32(oacc[i][0]); o.y = rtf32(oacc[i][1]);
        o.z = rtf32(oacc[i][2]); o.w = rtf32(oacc[i][3]);
        *reinterpret_cast<float4*>(dst) = o;
    }
}

// ---------------------------------------------------------------------------
extern "C" void kernel_launch(void* const* d_in, const int* in_sizes, int n_in,
                              void* d_out, int out_size)
{
    const float* values   = (const float*)d_in[0];
    const float* W_kqv    = (const float*)d_in[1];
    const float* b_kqv    = (const float*)d_in[2];
    const float* ln_gamma = (const float*)d_in[3];
    const float* ln_beta  = (const float*)d_in[4];
    const float* W_kernel = (const float*)d_in[5];
    const float* b_kernel = (const float*)d_in[6];
    const float* W_proj   = (const float*)d_in[7];
    const float* b_proj   = (const float*)d_in[8];
    float* out = (float*)d_out;

    float *kqv, *ctx, *x1, *va, *wq, *wk, *wp;
    cudaGetSymbolAddress((void**)&kqv, g_kqv);
    cudaGetSymbolAddress((void**)&ctx, g_ctx);
    cudaGetSymbolAddress((void**)&x1,  g_x1);
    cudaGetSymbolAddress((void**)&va,  g_va);
    cudaGetSymbolAddress((void**)&wq,  g_wq);
    cudaGetSymbolAddress((void**)&wk,  g_wk);
    cudaGetSymbolAddress((void**)&wp,  g_wp);

    const int attnSmem = (2 * KW * KSTR + QT * KSTR) * sizeof(float);

    static bool attrSet = false;
    if (!attrSet) {
        cudaFuncSetAttribute(attn_tile_kernel,
                             cudaFuncAttributeMaxDynamicSharedMemorySize, attnSmem);
        cudaFuncSetAttribute(tgemm_k<0>,
                             cudaFuncAttributeMaxDynamicSharedMemorySize, GEMM_SMEM);
        cudaFuncSetAttribute(tgemm_k<1>,
                             cudaFuncAttributeMaxDynamicSharedMemorySize, GEMM_SMEM);
        cudaFuncSetAttribute(tgemm_k<2>,
                             cudaFuncAttributeMaxDynamicSharedMemorySize, GEMM_SMEM);
        attrSet = true;
    }

    // 0) one fused tf32 rounding pass over values + all weights
    tf32_round_all<<<R_WP / 256, 256>>>(values, W_kqv, W_kernel, W_proj,
                                        va, wq, wk, wp);

    // 1) kqv = values @ W_kqv + b_kqv
    tgemm_k<0><<<dim3(D3 / 128, TT / 128), 256, GEMM_SMEM>>>(
        va, wq, b_kqv, nullptr, 0, kqv, TT, D3, DD);

    // 2) LayerNorm q and k in place
    ln_kernel<<<dim3(TT, 2), 128>>>(kqv, ln_gamma, ln_beta);

    // 3) attention -> ctx (tf32-rounded)
    attn_tile_kernel<<<dim3(SS / QT, HH, BB), 128, attnSmem>>>(kqv, ctx);

    // 4) x1 = relu(ctx @ W_kernel + b_kernel) (tf32-rounded out)
    tgemm_k<1><<<dim3(KSZ / 128, TT / 128), 256, GEMM_SMEM>>>(
        ctx, wk, b_kernel, nullptr, 0, x1, TT, KSZ, DD);

    // 5) out = x1 @ W_proj + b_proj + v
    tgemm_k<2><<<dim3(DD / 128, TT / 128), 256, GEMM_SMEM>>>(
        x1, wp, b_proj, kqv + 2 * DD, D3, out, TT, DD, KSZ);
}